// round 6
// baseline (speedup 1.0000x reference)
#include <cuda_runtime.h>
#include <math.h>

#define NN 1024
#define FD 32
#define ED 20
#define JT 64   // j-tile per iteration

// Packed scratch:
//  g_leftp[j*32+f] = (La[f], Lb[f], Lc[f], 0)   -- msg_left output, component-packed
//  g_vpack[j*32+f] = (V[j,0,f], V[j,1,f], V[j,2,f], 0)
__device__ float4 g_leftp[NN * 32];
__device__ float4 g_vpack[NN * 32];

// ---------------------------------------------------------------------------
// Kernel 1: per-node msg_left MLP + repack left and vector into float4 form.
// grid = NN, block = 96   (verified in R3)
// ---------------------------------------------------------------------------
__global__ void left_kernel(const float* __restrict__ scalar,
                            const float* __restrict__ vector,
                            const float* __restrict__ w1, const float* __restrict__ b1,
                            const float* __restrict__ w2, const float* __restrict__ b2) {
    int j = blockIdx.x;
    int t = threadIdx.x;
    __shared__ float ss[FD];
    __shared__ float sh[FD];
    if (t < FD) ss[t] = scalar[j * FD + t];
    __syncthreads();
    if (t < FD) {
        float acc = b1[t];
#pragma unroll
        for (int k = 0; k < FD; k++) acc += ss[k] * w1[k * FD + t];
        sh[t] = acc / (1.0f + expf(-acc));   // silu
    }
    __syncthreads();
    float acc = b2[t];
#pragma unroll
    for (int k = 0; k < FD; k++) acc += sh[k] * w2[k * 96 + t];

    int comp = t >> 5, f = t & 31;
    float* lp = (float*)g_leftp;
    float* vp = (float*)g_vpack;
    lp[(j * 32 + f) * 4 + comp] = acc;
    vp[(j * 32 + f) * 4 + comp] = vector[j * 96 + t];
    if (t < 32) {
        lp[(j * 32 + f) * 4 + 3] = 0.f;
        vp[(j * 32 + f) * 4 + 3] = 0.f;
    }
}

// ---------------------------------------------------------------------------
// Kernel 2: fused message-reduction + update, one CTA per node i.
// block = 256 (8 warps). Each warp handles 8 j's per 64-j tile; lane = feature.
// Pure fp32 FFMA; all bulk traffic via 128-bit loads.
// ---------------------------------------------------------------------------
__global__ void __launch_bounds__(256)
main_kernel(const float* __restrict__ scalar, const float* __restrict__ vector,
            const float* __restrict__ expansion, const float* __restrict__ direction,
            const float* __restrict__ mask,
            const float* __restrict__ mRw, const float* __restrict__ mRb,
            const float* __restrict__ uRw1, const float* __restrict__ uRb1,
            const float* __restrict__ uRw2, const float* __restrict__ uRb2,
            const float* __restrict__ Uw, const float* __restrict__ Vw,
            float* __restrict__ out) {
    int i = blockIdx.x;
    int tid = threadIdx.x;
    int warp = tid >> 5, lane = tid & 31;

    __shared__ float sX[JT * ED];      // expansion tile (row stride 20 floats = 80B, 16B-aligned)
    __shared__ float sMask[JT];
    __shared__ float4 sDir4[JT];       // (d0,d1,d2,pad)
    __shared__ float red[8][4][32];    // per-warp partial accumulators
    __shared__ float ds[32], dv[96];
    __shared__ float s_new[32], v_new[96], lu[96], ru[96], feats[64], hbuf[32], og[96];

    // mR_w columns owned by this lane, in registers (60 regs).
    float wa[ED], wb[ED], wc[ED];
#pragma unroll
    for (int e = 0; e < ED; e++) {
        wa[e] = mRw[e * 96 + lane];
        wb[e] = mRw[e * 96 + 32 + lane];
        wc[e] = mRw[e * 96 + 64 + lane];
    }
    const float rba = mRb[lane], rbb = mRb[32 + lane], rbc = mRb[64 + lane];

    float acc_s = 0.f, acc_v0 = 0.f, acc_v1 = 0.f, acc_v2 = 0.f;

    const float* Xrow = expansion + (size_t)i * NN * ED;
    const float* Mrow = mask + (size_t)i * NN;
    const float* Drow = direction + (size_t)i * NN * 3;

    for (int j0 = 0; j0 < NN; j0 += JT) {
        __syncthreads();   // previous tile fully consumed
        // cooperative tile loads (contiguous float4)
        {
            const float4* src = (const float4*)(Xrow + j0 * ED);   // 320 float4
#pragma unroll
            for (int k = tid; k < JT * ED / 4; k += 256) ((float4*)sX)[k] = src[k];
            if (tid < JT) sMask[tid] = Mrow[j0 + tid];
            for (int k = tid; k < JT * 3; k += 256)
                ((float*)sDir4)[(k / 3) * 4 + (k % 3)] = Drow[j0 * 3 + k];
        }
        __syncthreads();

#pragma unroll 4
        for (int t = 0; t < 8; t++) {
            int jj = warp * 8 + t;
            int j = j0 + jj;

            // 20->96 matvec: 5 broadcast LDS.128 + 60 FFMA
            const float4* xp = (const float4*)(sX + jj * ED);
            float4 x0 = xp[0], x1 = xp[1], x2 = xp[2], x3 = xp[3], x4 = xp[4];
            float ra = rba, rb = rbb, rc = rbc;
#define STEP(xc, e)                         \
            ra = fmaf(xc, wa[e], ra);       \
            rb = fmaf(xc, wb[e], rb);       \
            rc = fmaf(xc, wc[e], rc);
            STEP(x0.x, 0)  STEP(x0.y, 1)  STEP(x0.z, 2)  STEP(x0.w, 3)
            STEP(x1.x, 4)  STEP(x1.y, 5)  STEP(x1.z, 6)  STEP(x1.w, 7)
            STEP(x2.x, 8)  STEP(x2.y, 9)  STEP(x2.z, 10) STEP(x2.w, 11)
            STEP(x3.x, 12) STEP(x3.y, 13) STEP(x3.z, 14) STEP(x3.w, 15)
            STEP(x4.x, 16) STEP(x4.y, 17) STEP(x4.z, 18) STEP(x4.w, 19)
#undef STEP

            float4 L  = g_leftp[j * 32 + lane];   // LDG.128
            float4 Vv = g_vpack[j * 32 + lane];   // LDG.128
            float4 D  = sDir4[jj];                // LDS.128 broadcast
            float m   = sMask[jj];

            float mLa = m * L.x, mLb = m * L.y, mLc = m * L.z;
            acc_s = fmaf(mLb, rb, acc_s);
            float pa = mLa * ra, pc = mLc * rc;
            acc_v0 = fmaf(Vv.x, pa, acc_v0); acc_v0 = fmaf(D.x, pc, acc_v0);
            acc_v1 = fmaf(Vv.y, pa, acc_v1); acc_v1 = fmaf(D.y, pc, acc_v1);
            acc_v2 = fmaf(Vv.z, pa, acc_v2); acc_v2 = fmaf(D.z, pc, acc_v2);
        }
    }

    // cross-warp reduction
    red[warp][0][lane] = acc_s;
    red[warp][1][lane] = acc_v0;
    red[warp][2][lane] = acc_v1;
    red[warp][3][lane] = acc_v2;
    __syncthreads();
    if (tid < 128) {
        int a = tid >> 5, f = tid & 31;
        float s = 0.f;
#pragma unroll
        for (int w = 0; w < 8; w++) s += red[w][a][f];
        if (a == 0) ds[f] = s; else dv[(a - 1) * 32 + f] = s;
    }
    __syncthreads();

    // ---- update phase (per-node, tiny; verified in R2) ----
    if (tid < 32) s_new[tid] = scalar[i * 32 + tid] + ds[tid];
    if (tid < 96) v_new[tid] = vector[i * 96 + tid] + dv[tid];
    __syncthreads();

    if (tid < 96) {  // left = v_new @ U_w, right = v_new @ V_w
        int d = tid >> 5, f = tid & 31;
        float a1 = 0.f, a2 = 0.f;
#pragma unroll
        for (int k = 0; k < 32; k++) {
            float v = v_new[d * 32 + k];
            a1 += v * Uw[k * 32 + f];
            a2 += v * Vw[k * 32 + f];
        }
        lu[tid] = a1;
        ru[tid] = a2;
    }
    __syncthreads();
    if (tid < 32) {
        float r0 = ru[tid], r1 = ru[32 + tid], r2 = ru[64 + tid];
        feats[tid] = s_new[tid];
        feats[32 + tid] = sqrtf(r0 * r0 + r1 * r1 + r2 * r2);
    }
    __syncthreads();
    if (tid < 32) {
        float acc = uRb1[tid];
#pragma unroll
        for (int k = 0; k < 64; k++) acc += feats[k] * uRw1[k * 32 + tid];
        hbuf[tid] = acc / (1.0f + expf(-acc));   // silu
    }
    __syncthreads();
    if (tid < 96) {
        float acc = uRb2[tid];
#pragma unroll
        for (int k = 0; k < 32; k++) acc += hbuf[k] * uRw2[k * 96 + tid];
        og[tid] = acc;
    }
    __syncthreads();
    if (tid < 32) {  // scalar out: s_new + inner*b + c
        float inner = lu[tid] * ru[tid] + lu[32 + tid] * ru[32 + tid] + lu[64 + tid] * ru[64 + tid];
        out[i * 32 + tid] = s_new[tid] + inner * og[32 + tid] + og[64 + tid];
    }
    if (tid < 96) {  // vector out: v_new + a*left
        out[NN * 32 + i * 96 + tid] = v_new[tid] + og[tid & 31] * lu[tid];
    }
}

// ---------------------------------------------------------------------------
// launch
// inputs (metadata order): 0 scalar, 1 vector, 2 expansion, 3 direction, 4 mask,
// 5 mL_w1, 6 mL_b1, 7 mL_w2, 8 mL_b2, 9 mR_w, 10 mR_b,
// 11 uR_w1, 12 uR_b1, 13 uR_w2, 14 uR_b2, 15 U_w, 16 V_w
// output: [scalar_out (1024*32) | vector_out (1024*96)] fp32
// ---------------------------------------------------------------------------
extern "C" void kernel_launch(void* const* d_in, const int* in_sizes, int n_in,
                              void* d_out, int out_size) {
    const float* scalar    = (const float*)d_in[0];
    const float* vector    = (const float*)d_in[1];
    const float* expansion = (const float*)d_in[2];
    const float* direction = (const float*)d_in[3];
    const float* mask      = (const float*)d_in[4];
    const float* mL_w1 = (const float*)d_in[5];
    const float* mL_b1 = (const float*)d_in[6];
    const float* mL_w2 = (const float*)d_in[7];
    const float* mL_b2 = (const float*)d_in[8];
    const float* mR_w  = (const float*)d_in[9];
    const float* mR_b  = (const float*)d_in[10];
    const float* uR_w1 = (const float*)d_in[11];
    const float* uR_b1 = (const float*)d_in[12];
    const float* uR_w2 = (const float*)d_in[13];
    const float* uR_b2 = (const float*)d_in[14];
    const float* U_w   = (const float*)d_in[15];
    const float* V_w   = (const float*)d_in[16];
    float* out = (float*)d_out;

    left_kernel<<<NN, 96>>>(scalar, vector, mL_w1, mL_b1, mL_w2, mL_b2);
    main_kernel<<<NN, 256>>>(scalar, vector, expansion, direction, mask,
                             mR_w, mR_b, uR_w1, uR_b1, uR_w2, uR_b2, U_w, V_w, out);
}

// round 7
// speedup vs baseline: 1.3968x; 1.3968x over previous
#include <cuda_runtime.h>
#include <math.h>

#define NN 1024
#define FD 32
#define ED 20
#define JT 64   // j-tile per iteration

// Packed scratch:
//  g_leftp[j*32+f] = (La[f], Lb[f], Lc[f], 0)   -- msg_left output, component-packed
//  g_vpack[j*32+f] = (V[j,0,f], V[j,1,f], V[j,2,f], 0)
__device__ float4 g_leftp[NN * 32];
__device__ float4 g_vpack[NN * 32];

// ---------------------------------------------------------------------------
// Kernel 1: per-node msg_left MLP + repack left and vector into float4 form.
// grid = NN, block = 96   (verified R3/R6)
// ---------------------------------------------------------------------------
__global__ void left_kernel(const float* __restrict__ scalar,
                            const float* __restrict__ vector,
                            const float* __restrict__ w1, const float* __restrict__ b1,
                            const float* __restrict__ w2, const float* __restrict__ b2) {
    int j = blockIdx.x;
    int t = threadIdx.x;
    __shared__ float ss[FD];
    __shared__ float sh[FD];
    if (t < FD) ss[t] = scalar[j * FD + t];
    __syncthreads();
    if (t < FD) {
        float acc = b1[t];
#pragma unroll
        for (int k = 0; k < FD; k++) acc += ss[k] * w1[k * FD + t];
        sh[t] = acc / (1.0f + expf(-acc));   // silu
    }
    __syncthreads();
    float acc = b2[t];
#pragma unroll
    for (int k = 0; k < FD; k++) acc += sh[k] * w2[k * 96 + t];

    int comp = t >> 5, f = t & 31;
    float* lp = (float*)g_leftp;
    float* vp = (float*)g_vpack;
    lp[(j * 32 + f) * 4 + comp] = acc;
    vp[(j * 32 + f) * 4 + comp] = vector[j * 96 + t];
    if (t < 32) {
        lp[(j * 32 + f) * 4 + 3] = 0.f;
        vp[(j * 32 + f) * 4 + 3] = 0.f;
    }
}

// ---------------------------------------------------------------------------
// Kernel 2: fused message-reduction + update, one CTA per node i.
// block = 256 (8 warps), HARD 2-CTA occupancy (<=128 regs).
// Each warp handles 8 j's per 64-j tile; lane = feature.
// ---------------------------------------------------------------------------
__global__ void __launch_bounds__(256, 2)
main_kernel(const float* __restrict__ scalar, const float* __restrict__ vector,
            const float* __restrict__ expansion, const float* __restrict__ direction,
            const float* __restrict__ mask,
            const float* __restrict__ mRw, const float* __restrict__ mRb,
            const float* __restrict__ uRw1, const float* __restrict__ uRb1,
            const float* __restrict__ uRw2, const float* __restrict__ uRb2,
            const float* __restrict__ Uw, const float* __restrict__ Vw,
            float* __restrict__ out) {
    int i = blockIdx.x;
    int tid = threadIdx.x;
    int warp = tid >> 5, lane = tid & 31;

    __shared__ float sX[JT * ED];      // expansion tile (row = 20 floats = 80B, 8B-aligned)
    __shared__ float sMask[JT];
    __shared__ float4 sDir4[JT];       // (d0,d1,d2,pad)
    __shared__ float red[8][4][32];    // per-warp partial accumulators
    __shared__ float ds[32], dv[96];
    __shared__ float s_new[32], v_new[96], lu[96], ru[96], feats[64], hbuf[32], og[96];

    // mR_w columns owned by this lane, in registers (60 regs).
    float wa[ED], wb[ED], wc[ED];
#pragma unroll
    for (int e = 0; e < ED; e++) {
        wa[e] = mRw[e * 96 + lane];
        wb[e] = mRw[e * 96 + 32 + lane];
        wc[e] = mRw[e * 96 + 64 + lane];
    }
    const float rba = mRb[lane], rbb = mRb[32 + lane], rbc = mRb[64 + lane];

    float acc_s = 0.f, acc_v0 = 0.f, acc_v1 = 0.f, acc_v2 = 0.f;

    const float* Xrow = expansion + (size_t)i * NN * ED;
    const float* Mrow = mask + (size_t)i * NN;
    const float* Drow = direction + (size_t)i * NN * 3;

    for (int j0 = 0; j0 < NN; j0 += JT) {
        __syncthreads();   // previous tile fully consumed
        // cooperative tile loads (contiguous float4)
        {
            const float4* src = (const float4*)(Xrow + j0 * ED);   // 320 float4
#pragma unroll
            for (int k = tid; k < JT * ED / 4; k += 256) ((float4*)sX)[k] = src[k];
            if (tid < JT) sMask[tid] = Mrow[j0 + tid];
            for (int k = tid; k < JT * 3; k += 256)
                ((float*)sDir4)[(k / 3) * 4 + (k % 3)] = Drow[j0 * 3 + k];
        }
        __syncthreads();

#pragma unroll 4
        for (int t = 0; t < 8; t++) {
            int jj = warp * 8 + t;
            int j = j0 + jj;

            // 20->96 matvec: 10 broadcast LDS.64 + 60 FFMA, low transient pressure
            const float2* xp = (const float2*)(sX + jj * ED);
            float ra = rba, rb = rbb, rc = rbc;
#define STEP2(q)                                         \
            {   float2 x = xp[q];                        \
                ra = fmaf(x.x, wa[2*(q)], ra);           \
                rb = fmaf(x.x, wb[2*(q)], rb);           \
                rc = fmaf(x.x, wc[2*(q)], rc);           \
                ra = fmaf(x.y, wa[2*(q)+1], ra);         \
                rb = fmaf(x.y, wb[2*(q)+1], rb);         \
                rc = fmaf(x.y, wc[2*(q)+1], rc);  }
            STEP2(0) STEP2(1) STEP2(2) STEP2(3) STEP2(4)
            STEP2(5) STEP2(6) STEP2(7) STEP2(8) STEP2(9)
#undef STEP2

            float4 L  = g_leftp[j * 32 + lane];   // LDG.128 (coalesced)
            float4 Vv = g_vpack[j * 32 + lane];   // LDG.128 (coalesced)
            float4 D  = sDir4[jj];                // LDS.128 broadcast
            float m   = sMask[jj];

            float mLa = m * L.x, mLb = m * L.y, mLc = m * L.z;
            acc_s = fmaf(mLb, rb, acc_s);
            float pa = mLa * ra, pc = mLc * rc;
            acc_v0 = fmaf(Vv.x, pa, acc_v0); acc_v0 = fmaf(D.x, pc, acc_v0);
            acc_v1 = fmaf(Vv.y, pa, acc_v1); acc_v1 = fmaf(D.y, pc, acc_v1);
            acc_v2 = fmaf(Vv.z, pa, acc_v2); acc_v2 = fmaf(D.z, pc, acc_v2);
        }
    }

    // cross-warp reduction
    red[warp][0][lane] = acc_s;
    red[warp][1][lane] = acc_v0;
    red[warp][2][lane] = acc_v1;
    red[warp][3][lane] = acc_v2;
    __syncthreads();
    if (tid < 128) {
        int a = tid >> 5, f = tid & 31;
        float s = 0.f;
#pragma unroll
        for (int w = 0; w < 8; w++) s += red[w][a][f];
        if (a == 0) ds[f] = s; else dv[(a - 1) * 32 + f] = s;
    }
    __syncthreads();

    // ---- update phase (per-node, tiny; verified in R2) ----
    if (tid < 32) s_new[tid] = scalar[i * 32 + tid] + ds[tid];
    if (tid < 96) v_new[tid] = vector[i * 96 + tid] + dv[tid];
    __syncthreads();

    if (tid < 96) {  // left = v_new @ U_w, right = v_new @ V_w
        int d = tid >> 5, f = tid & 31;
        float a1 = 0.f, a2 = 0.f;
#pragma unroll
        for (int k = 0; k < 32; k++) {
            float v = v_new[d * 32 + k];
            a1 += v * Uw[k * 32 + f];
            a2 += v * Vw[k * 32 + f];
        }
        lu[tid] = a1;
        ru[tid] = a2;
    }
    __syncthreads();
    if (tid < 32) {
        float r0 = ru[tid], r1 = ru[32 + tid], r2 = ru[64 + tid];
        feats[tid] = s_new[tid];
        feats[32 + tid] = sqrtf(r0 * r0 + r1 * r1 + r2 * r2);
    }
    __syncthreads();
    if (tid < 32) {
        float acc = uRb1[tid];
#pragma unroll
        for (int k = 0; k < 64; k++) acc += feats[k] * uRw1[k * 32 + tid];
        hbuf[tid] = acc / (1.0f + expf(-acc));   // silu
    }
    __syncthreads();
    if (tid < 96) {
        float acc = uRb2[tid];
#pragma unroll
        for (int k = 0; k < 32; k++) acc += hbuf[k] * uRw2[k * 96 + tid];
        og[tid] = acc;
    }
    __syncthreads();
    if (tid < 32) {  // scalar out: s_new + inner*b + c
        float inner = lu[tid] * ru[tid] + lu[32 + tid] * ru[32 + tid] + lu[64 + tid] * ru[64 + tid];
        out[i * 32 + tid] = s_new[tid] + inner * og[32 + tid] + og[64 + tid];
    }
    if (tid < 96) {  // vector out: v_new + a*left
        out[NN * 32 + i * 96 + tid] = v_new[tid] + og[tid & 31] * lu[tid];
    }
}

// ---------------------------------------------------------------------------
// launch
// inputs (metadata order): 0 scalar, 1 vector, 2 expansion, 3 direction, 4 mask,
// 5 mL_w1, 6 mL_b1, 7 mL_w2, 8 mL_b2, 9 mR_w, 10 mR_b,
// 11 uR_w1, 12 uR_b1, 13 uR_w2, 14 uR_b2, 15 U_w, 16 V_w
// output: [scalar_out (1024*32) | vector_out (1024*96)] fp32
// ---------------------------------------------------------------------------
extern "C" void kernel_launch(void* const* d_in, const int* in_sizes, int n_in,
                              void* d_out, int out_size) {
    const float* scalar    = (const float*)d_in[0];
    const float* vector    = (const float*)d_in[1];
    const float* expansion = (const float*)d_in[2];
    const float* direction = (const float*)d_in[3];
    const float* mask      = (const float*)d_in[4];
    const float* mL_w1 = (const float*)d_in[5];
    const float* mL_b1 = (const float*)d_in[6];
    const float* mL_w2 = (const float*)d_in[7];
    const float* mL_b2 = (const float*)d_in[8];
    const float* mR_w  = (const float*)d_in[9];
    const float* mR_b  = (const float*)d_in[10];
    const float* uR_w1 = (const float*)d_in[11];
    const float* uR_b1 = (const float*)d_in[12];
    const float* uR_w2 = (const float*)d_in[13];
    const float* uR_b2 = (const float*)d_in[14];
    const float* U_w   = (const float*)d_in[15];
    const float* V_w   = (const float*)d_in[16];
    float* out = (float*)d_out;

    left_kernel<<<NN, 96>>>(scalar, vector, mL_w1, mL_b1, mL_w2, mL_b2);
    main_kernel<<<NN, 256>>>(scalar, vector, expansion, direction, mask,
                             mR_w, mR_b, uR_w1, uR_b1, uR_w2, uR_b2, U_w, V_w, out);
}

// round 8
// speedup vs baseline: 1.4506x; 1.0386x over previous
#include <cuda_runtime.h>
#include <math.h>
#include <stdint.h>

#define NN 1024
#define FD 32
#define ED 20
#define JT 64   // j-tile per iteration

typedef unsigned long long ull;

// Packed scratch:
//  g_leftp[j*32+f] = (La[f], Lb[f], Lc[f], 0)   -- msg_left output, component-packed
//  g_vpack[j*32+f] = (V[j,0,f], V[j,1,f], V[j,2,f], 0)
__device__ float4 g_leftp[NN * 32];
__device__ float4 g_vpack[NN * 32];

// ---- f32x2 helpers: natural-pair FFMA2 (no duplication, no repacking) ----
__device__ __forceinline__ ull ffma2(ull a, ull b, ull c) {
    ull d; asm("fma.rn.f32x2 %0, %1, %2, %3;" : "=l"(d) : "l"(a), "l"(b), "l"(c)); return d;
}
__device__ __forceinline__ ull pack2(float lo, float hi) {
    ull r; asm("mov.b64 %0, {%1, %2};" : "=l"(r) : "f"(lo), "f"(hi)); return r;
}
__device__ __forceinline__ float f2lo(ull p) { return __int_as_float((int)(unsigned)p); }
__device__ __forceinline__ float f2hi(ull p) { return __int_as_float((int)(p >> 32)); }

// ---------------------------------------------------------------------------
// Kernel 1: per-node msg_left MLP + repack left and vector into float4 form.
// grid = NN, block = 96   (verified R3/R6/R7)
// ---------------------------------------------------------------------------
__global__ void left_kernel(const float* __restrict__ scalar,
                            const float* __restrict__ vector,
                            const float* __restrict__ w1, const float* __restrict__ b1,
                            const float* __restrict__ w2, const float* __restrict__ b2) {
    int j = blockIdx.x;
    int t = threadIdx.x;
    __shared__ float ss[FD];
    __shared__ float sh[FD];
    if (t < FD) ss[t] = scalar[j * FD + t];
    __syncthreads();
    if (t < FD) {
        float acc = b1[t];
#pragma unroll
        for (int k = 0; k < FD; k++) acc += ss[k] * w1[k * FD + t];
        sh[t] = acc / (1.0f + expf(-acc));   // silu
    }
    __syncthreads();
    float acc = b2[t];
#pragma unroll
    for (int k = 0; k < FD; k++) acc += sh[k] * w2[k * 96 + t];

    int comp = t >> 5, f = t & 31;
    float* lp = (float*)g_leftp;
    float* vp = (float*)g_vpack;
    lp[(j * 32 + f) * 4 + comp] = acc;
    vp[(j * 32 + f) * 4 + comp] = vector[j * 96 + t];
    if (t < 32) {
        lp[(j * 32 + f) * 4 + 3] = 0.f;
        vp[(j * 32 + f) * 4 + 3] = 0.f;
    }
}

// ---------------------------------------------------------------------------
// Kernel 2: fused message-reduction + update, one CTA per node i.
// block = 256 (8 warps), hard 2-CTA occupancy (<=128 regs).
// Each warp handles 8 j's per 64-j tile; lane = feature.
// Matvec via e-paired fma.rn.f32x2: a=(x_e,x_{e+1}) natural float2 from smem,
// b=(w_e,w_{e+1}) pre-packed registers, even/odd partial sums.
// ---------------------------------------------------------------------------
__global__ void __launch_bounds__(256, 2)
main_kernel(const float* __restrict__ scalar, const float* __restrict__ vector,
            const float* __restrict__ expansion, const float* __restrict__ direction,
            const float* __restrict__ mask,
            const float* __restrict__ mRw, const float* __restrict__ mRb,
            const float* __restrict__ uRw1, const float* __restrict__ uRb1,
            const float* __restrict__ uRw2, const float* __restrict__ uRb2,
            const float* __restrict__ Uw, const float* __restrict__ Vw,
            float* __restrict__ out) {
    int i = blockIdx.x;
    int tid = threadIdx.x;
    int warp = tid >> 5, lane = tid & 31;

    __shared__ float sX[JT * ED];      // expansion tile (row = 20 floats = 80B, 8B-aligned)
    __shared__ float sMask[JT];
    __shared__ float4 sDir4[JT];       // (d0,d1,d2,pad)
    __shared__ float red[8][4][32];    // per-warp partial accumulators
    __shared__ float ds[32], dv[96];
    __shared__ float s_new[32], v_new[96], lu[96], ru[96], feats[64], hbuf[32], og[96];

    // mR_w columns owned by this lane, packed as e-pairs (60 regs total).
    ull wA[ED / 2], wB[ED / 2], wC[ED / 2];
#pragma unroll
    for (int q = 0; q < ED / 2; q++) {
        wA[q] = pack2(mRw[(2 * q) * 96 + lane],      mRw[(2 * q + 1) * 96 + lane]);
        wB[q] = pack2(mRw[(2 * q) * 96 + 32 + lane], mRw[(2 * q + 1) * 96 + 32 + lane]);
        wC[q] = pack2(mRw[(2 * q) * 96 + 64 + lane], mRw[(2 * q + 1) * 96 + 64 + lane]);
    }
    const ull biasA = pack2(mRb[lane], 0.f);
    const ull biasB = pack2(mRb[32 + lane], 0.f);
    const ull biasC = pack2(mRb[64 + lane], 0.f);

    float acc_s = 0.f, acc_v0 = 0.f, acc_v1 = 0.f, acc_v2 = 0.f;

    const float* Xrow = expansion + (size_t)i * NN * ED;
    const float* Mrow = mask + (size_t)i * NN;
    const float* Drow = direction + (size_t)i * NN * 3;

    for (int j0 = 0; j0 < NN; j0 += JT) {
        __syncthreads();   // previous tile fully consumed
        // cooperative tile loads (contiguous float4)
        {
            const float4* src = (const float4*)(Xrow + j0 * ED);   // 320 float4
#pragma unroll
            for (int k = tid; k < JT * ED / 4; k += 256) ((float4*)sX)[k] = src[k];
            if (tid < JT) sMask[tid] = Mrow[j0 + tid];
            for (int k = tid; k < JT * 3; k += 256)
                ((float*)sDir4)[(k / 3) * 4 + (k % 3)] = Drow[j0 * 3 + k];
        }
        __syncthreads();

#pragma unroll 4
        for (int t = 0; t < 8; t++) {
            int jj = warp * 8 + t;
            int j = j0 + jj;

            // 20->96 matvec: 10 broadcast LDS.64 + 30 FFMA2 + 3 FADD
            const ull* xp = (const ull*)(sX + jj * ED);   // (x_{2q}, x_{2q+1}) pairs
            ull pa2 = biasA, pb2 = biasB, pc2 = biasC;
#pragma unroll
            for (int q = 0; q < ED / 2; q++) {
                ull x2 = xp[q];
                pa2 = ffma2(x2, wA[q], pa2);
                pb2 = ffma2(x2, wB[q], pb2);
                pc2 = ffma2(x2, wC[q], pc2);
            }
            float ra = f2lo(pa2) + f2hi(pa2);
            float rb = f2lo(pb2) + f2hi(pb2);
            float rc = f2lo(pc2) + f2hi(pc2);

            float4 L  = g_leftp[j * 32 + lane];   // LDG.128 (coalesced)
            float4 Vv = g_vpack[j * 32 + lane];   // LDG.128 (coalesced)
            float4 D  = sDir4[jj];                // LDS.128 broadcast
            float m   = sMask[jj];

            float mLa = m * L.x, mLb = m * L.y, mLc = m * L.z;
            acc_s = fmaf(mLb, rb, acc_s);
            float pa = mLa * ra, pc = mLc * rc;
            acc_v0 = fmaf(Vv.x, pa, acc_v0); acc_v0 = fmaf(D.x, pc, acc_v0);
            acc_v1 = fmaf(Vv.y, pa, acc_v1); acc_v1 = fmaf(D.y, pc, acc_v1);
            acc_v2 = fmaf(Vv.z, pa, acc_v2); acc_v2 = fmaf(D.z, pc, acc_v2);
        }
    }

    // cross-warp reduction
    red[warp][0][lane] = acc_s;
    red[warp][1][lane] = acc_v0;
    red[warp][2][lane] = acc_v1;
    red[warp][3][lane] = acc_v2;
    __syncthreads();
    if (tid < 128) {
        int a = tid >> 5, f = tid & 31;
        float s = 0.f;
#pragma unroll
        for (int w = 0; w < 8; w++) s += red[w][a][f];
        if (a == 0) ds[f] = s; else dv[(a - 1) * 32 + f] = s;
    }
    __syncthreads();

    // ---- update phase (per-node, tiny; verified in R2) ----
    if (tid < 32) s_new[tid] = scalar[i * 32 + tid] + ds[tid];
    if (tid < 96) v_new[tid] = vector[i * 96 + tid] + dv[tid];
    __syncthreads();

    if (tid < 96) {  // left = v_new @ U_w, right = v_new @ V_w
        int d = tid >> 5, f = tid & 31;
        float a1 = 0.f, a2 = 0.f;
#pragma unroll
        for (int k = 0; k < 32; k++) {
            float v = v_new[d * 32 + k];
            a1 += v * Uw[k * 32 + f];
            a2 += v * Vw[k * 32 + f];
        }
        lu[tid] = a1;
        ru[tid] = a2;
    }
    __syncthreads();
    if (tid < 32) {
        float r0 = ru[tid], r1 = ru[32 + tid], r2 = ru[64 + tid];
        feats[tid] = s_new[tid];
        feats[32 + tid] = sqrtf(r0 * r0 + r1 * r1 + r2 * r2);
    }
    __syncthreads();
    if (tid < 32) {
        float acc = uRb1[tid];
#pragma unroll
        for (int k = 0; k < 64; k++) acc += feats[k] * uRw1[k * 32 + tid];
        hbuf[tid] = acc / (1.0f + expf(-acc));   // silu
    }
    __syncthreads();
    if (tid < 96) {
        float acc = uRb2[tid];
#pragma unroll
        for (int k = 0; k < 32; k++) acc += hbuf[k] * uRw2[k * 96 + tid];
        og[tid] = acc;
    }
    __syncthreads();
    if (tid < 32) {  // scalar out: s_new + inner*b + c
        float inner = lu[tid] * ru[tid] + lu[32 + tid] * ru[32 + tid] + lu[64 + tid] * ru[64 + tid];
        out[i * 32 + tid] = s_new[tid] + inner * og[32 + tid] + og[64 + tid];
    }
    if (tid < 96) {  // vector out: v_new + a*left
        out[NN * 32 + i * 96 + tid] = v_new[tid] + og[tid & 31] * lu[tid];
    }
}

// ---------------------------------------------------------------------------
// launch
// inputs (metadata order): 0 scalar, 1 vector, 2 expansion, 3 direction, 4 mask,
// 5 mL_w1, 6 mL_b1, 7 mL_w2, 8 mL_b2, 9 mR_w, 10 mR_b,
// 11 uR_w1, 12 uR_b1, 13 uR_w2, 14 uR_b2, 15 U_w, 16 V_w
// output: [scalar_out (1024*32) | vector_out (1024*96)] fp32
// ---------------------------------------------------------------------------
extern "C" void kernel_launch(void* const* d_in, const int* in_sizes, int n_in,
                              void* d_out, int out_size) {
    const float* scalar    = (const float*)d_in[0];
    const float* vector    = (const float*)d_in[1];
    const float* expansion = (const float*)d_in[2];
    const float* direction = (const float*)d_in[3];
    const float* mask      = (const float*)d_in[4];
    const float* mL_w1 = (const float*)d_in[5];
    const float* mL_b1 = (const float*)d_in[6];
    const float* mL_w2 = (const float*)d_in[7];
    const float* mL_b2 = (const float*)d_in[8];
    const float* mR_w  = (const float*)d_in[9];
    const float* mR_b  = (const float*)d_in[10];
    const float* uR_w1 = (const float*)d_in[11];
    const float* uR_b1 = (const float*)d_in[12];
    const float* uR_w2 = (const float*)d_in[13];
    const float* uR_b2 = (const float*)d_in[14];
    const float* U_w   = (const float*)d_in[15];
    const float* V_w   = (const float*)d_in[16];
    float* out = (float*)d_out;

    left_kernel<<<NN, 96>>>(scalar, vector, mL_w1, mL_b1, mL_w2, mL_b2);
    main_kernel<<<NN, 256>>>(scalar, vector, expansion, direction, mask,
                             mR_w, mR_b, uR_w1, uR_b1, uR_w2, uR_b2, U_w, V_w, out);
}